// round 17
// baseline (speedup 1.0000x reference)
#include <cuda_runtime.h>

#define NN 100000
#define EE 1600000
#define LL 3
#define CAP 96
#define GNPB 128
#define GPAD 132
#define ZPAD 66

typedef unsigned long long ull;

__device__ float g_h[NN * 64];
__device__ float g_agg[NN * 64];
__device__ float g_z1[NN * 64];
__device__ float g_z2[NN * 64];
__device__ float g_stats[LL * 256];
__device__ int   g_deg[NN];
__device__ int   g_csr[(size_t)NN * CAP];

__device__ __forceinline__ ull pack2(float a, float b) {
    ull r;
    asm("mov.b64 %0, {%1, %2};" : "=l"(r) : "f"(a), "f"(b));
    return r;
}
__device__ __forceinline__ float2 unpack2(ull v) {
    float2 r;
    asm("mov.b64 {%0, %1}, %2;" : "=f"(r.x), "=f"(r.y) : "l"(v));
    return r;
}
__device__ __forceinline__ void ffma2(ull& d, ull a, ull b) {
    asm("fma.rn.f32x2 %0, %1, %2, %0;" : "+l"(d) : "l"(a), "l"(b));
}
__device__ __forceinline__ void fadd2(ull& d, ull a) {
    asm("add.rn.f32x2 %0, %0, %1;" : "+l"(d) : "l"(a));
}

__global__ void __launch_bounds__(1024) kzero() {
    int t = blockIdx.x * 1024 + threadIdx.x;
    if (t < NN) g_deg[t] = 0;
    if (t < LL * 256) g_stats[t] = 0.f;
}

__global__ void __launch_bounds__(256) kfill(const int* __restrict__ ei) {
    int e = blockIdx.x * 256 + threadIdx.x;
    if (e >= EE) return;
    int s = ei[e];
    int d = ei[EE + e];
    int pos = atomicAdd(&g_deg[d], 1);
    if (pos < CAP) g_csr[(size_t)d * CAP + pos] = s;
}

__global__ void __launch_bounds__(256) kinit(const float* __restrict__ x,
                                             const float* __restrict__ fcW,
                                             const float* __restrict__ fcb,
                                             float* __restrict__ out) {
    __shared__ float fw[640];
    __shared__ float bsum[10];
    int tid = threadIdx.x;
    for (int i = tid; i < 640; i += 256) fw[i] = fcW[i];
    if (tid < 10) {
        float b = 0.f;
        for (int l = 0; l < LL + 1; l++) b += fcb[l * 10 + tid];
        bsum[tid] = b;
    }
    __syncthreads();
    int n = blockIdx.x * 256 + tid;
    if (n >= NN) return;
    float acc[10];
#pragma unroll
    for (int c = 0; c < 10; c++) acc[c] = bsum[c];
    const float4* x4 = ((const float4*)x) + (size_t)n * 16;
#pragma unroll
    for (int kk = 0; kk < 16; kk++) {
        float4 v = x4[kk];
        const float* r0 = fw + (kk * 4) * 10;
#pragma unroll
        for (int c = 0; c < 10; c++)
            acc[c] += v.x * r0[c] + v.y * r0[10 + c] + v.z * r0[20 + c] + v.w * r0[30 + c];
    }
#pragma unroll
    for (int c = 0; c < 10; c++) out[n * 10 + c] = acc[c];
}

__global__ void __launch_bounds__(256) kgather(const float* __restrict__ x, int use_x) {
    int w = (blockIdx.x * 256 + threadIdx.x) >> 5;
    int l = threadIdx.x & 31;
    if (w >= NN) return;
    const float* hin = use_x ? x : g_h;
    int deg = g_deg[w];
    if (deg > CAP) deg = CAP;
    const int* adj = g_csr + (size_t)w * CAP;
    float2 self = ((const float2*)(hin + (size_t)w * 64))[l];
    float a0x = self.x, a0y = self.y;
    float a1x = 0.f, a1y = 0.f, a2x = 0.f, a2y = 0.f, a3x = 0.f, a3y = 0.f;
    int e = 0;
    for (; e + 4 <= deg; e += 4) {
        int i0 = adj[e], i1 = adj[e + 1], i2 = adj[e + 2], i3 = adj[e + 3];
        float2 v0 = ((const float2*)(hin + (size_t)i0 * 64))[l];
        float2 v1 = ((const float2*)(hin + (size_t)i1 * 64))[l];
        float2 v2 = ((const float2*)(hin + (size_t)i2 * 64))[l];
        float2 v3 = ((const float2*)(hin + (size_t)i3 * 64))[l];
        a0x += v0.x; a0y += v0.y;
        a1x += v1.x; a1y += v1.y;
        a2x += v2.x; a2y += v2.y;
        a3x += v3.x; a3y += v3.y;
    }
    for (; e < deg; e++) {
        float2 v0 = ((const float2*)(hin + (size_t)adj[e] * 64))[l];
        a0x += v0.x; a0y += v0.y;
    }
    float2 r;
    r.x = (a0x + a1x) + (a2x + a3x);
    r.y = (a0y + a1y) + (a2y + a3y);
    ((float2*)g_agg)[(size_t)w * 32 + l] = r;
}

// ======== kG: [BN+ReLU] -> smem(T) -> col-pair-packed GEMM -> z + stats =========
// 256 threads, 128 nodes/block. Thread tile: 4 nodes x 8 cols, acc = col-pairs.
__global__ void __launch_bounds__(256) kG(const float* __restrict__ W,
                                          const float* __restrict__ b,
                                          const float* __restrict__ gam,
                                          const float* __restrict__ bet,
                                          int layer, int mode) {
    __shared__ float y_s[64 * GPAD];   // reused as z_s[128][ZPAD]
    __shared__ float Wsh[4096];
    __shared__ float bs[64], sA[64], sB[64];
    const float* in = mode ? g_z1 : g_agg;
    float* zout = mode ? g_z2 : g_z1;
    int tid = threadIdx.x, lane = tid & 31;
    const float4* Wg = (const float4*)W;
    for (int i = tid; i < 1024; i += 256) ((float4*)Wsh)[i] = Wg[i];
    if (tid < 64) {
        bs[tid] = b[tid];
        if (mode) {
            float s = g_stats[layer * 256 + tid];
            float q = g_stats[layer * 256 + 64 + tid];
            float mu = s * (1.f / NN);
            float var = q * (1.f / NN) - mu * mu;
            float a = rsqrtf(var + 1e-5f) * gam[tid];
            sA[tid] = a;
            sB[tid] = bet[tid] - mu * a;
        }
    }
    __syncthreads();

    int base = blockIdx.x * GNPB;

    // ---- staging: coalesced row reads -> transposed y_s[k][node] ---------------
    {
        int nl0 = tid >> 4;       // 0..15
        int c4 = tid & 15;
        int k0 = 4 * c4;
#pragma unroll 4
        for (int p = 0; p < 8; p++) {
            int nl = p * 16 + nl0;
            int n = base + nl;
            float4 v = make_float4(0.f, 0.f, 0.f, 0.f);
            if (n < NN) {
                v = *(const float4*)(in + (size_t)n * 64 + k0);
                if (mode) {
                    v.x = fmaxf(fmaf(v.x, sA[k0 + 0], sB[k0 + 0]), 0.f);
                    v.y = fmaxf(fmaf(v.y, sA[k0 + 1], sB[k0 + 1]), 0.f);
                    v.z = fmaxf(fmaf(v.z, sA[k0 + 2], sB[k0 + 2]), 0.f);
                    v.w = fmaxf(fmaf(v.w, sA[k0 + 3], sB[k0 + 3]), 0.f);
                }
            }
            y_s[(k0 + 0) * GPAD + nl] = v.x;
            y_s[(k0 + 1) * GPAD + nl] = v.y;
            y_s[(k0 + 2) * GPAD + nl] = v.z;
            y_s[(k0 + 3) * GPAD + nl] = v.w;
        }
    }
    __syncthreads();

    int ng = tid & 31;   // node group: nodes 4ng..4ng+3 (warp = one col group)
    int cg = tid >> 5;   // col group: cols 8cg..8cg+7
    // acc[i][j]: node 4ng+i, cols (8cg+2j, 8cg+2j+1) packed
    ull acc[4][4];
#pragma unroll
    for (int j = 0; j < 4; j++) {
        ull bp = pack2(bs[8 * cg + 2 * j], bs[8 * cg + 2 * j + 1]);
        acc[0][j] = bp; acc[1][j] = bp; acc[2][j] = bp; acc[3][j] = bp;
    }
#pragma unroll 8
    for (int k = 0; k < 64; k++) {
        float4 a4 = *(const float4*)(y_s + k * GPAD + 4 * ng);
        ulonglong2 wlo = *(const ulonglong2*)(Wsh + k * 64 + 8 * cg);
        ulonglong2 whi = *(const ulonglong2*)(Wsh + k * 64 + 8 * cg + 4);
        ull a;
        a = pack2(a4.x, a4.x);
        ffma2(acc[0][0], a, wlo.x); ffma2(acc[0][1], a, wlo.y);
        ffma2(acc[0][2], a, whi.x); ffma2(acc[0][3], a, whi.y);
        a = pack2(a4.y, a4.y);
        ffma2(acc[1][0], a, wlo.x); ffma2(acc[1][1], a, wlo.y);
        ffma2(acc[1][2], a, whi.x); ffma2(acc[1][3], a, whi.y);
        a = pack2(a4.z, a4.z);
        ffma2(acc[2][0], a, wlo.x); ffma2(acc[2][1], a, wlo.y);
        ffma2(acc[2][2], a, whi.x); ffma2(acc[2][3], a, whi.y);
        a = pack2(a4.w, a4.w);
        ffma2(acc[3][0], a, wlo.x); ffma2(acc[3][1], a, wlo.y);
        ffma2(acc[3][2], a, whi.x); ffma2(acc[3][3], a, whi.y);
    }

    // ---- stats: fully packed (sum, sum-of-squares), warp = one col group -------
    {
        ull s[4], q[4];
        ull z0 = pack2(0.f, 0.f);
#pragma unroll
        for (int j = 0; j < 4; j++) { s[j] = z0; q[j] = z0; }
#pragma unroll
        for (int i = 0; i < 4; i++) {
            if (base + 4 * ng + i < NN) {
#pragma unroll
                for (int j = 0; j < 4; j++) {
                    fadd2(s[j], acc[i][j]);
                    ffma2(q[j], acc[i][j], acc[i][j]);
                }
            }
        }
#pragma unroll
        for (int off = 16; off >= 1; off >>= 1) {
#pragma unroll
            for (int j = 0; j < 4; j++) {
                s[j] += 0;  // keep ull lvalue
                s[j] = pack2(unpack2(s[j]).x + __shfl_xor_sync(0xffffffffu, unpack2(s[j]).x, off),
                             unpack2(s[j]).y + __shfl_xor_sync(0xffffffffu, unpack2(s[j]).y, off));
                q[j] = pack2(unpack2(q[j]).x + __shfl_xor_sync(0xffffffffu, unpack2(q[j]).x, off),
                             unpack2(q[j]).y + __shfl_xor_sync(0xffffffffu, unpack2(q[j]).y, off));
            }
        }
        if (lane == 0) {
            float* st = g_stats + layer * 256 + (mode ? 128 : 0);
#pragma unroll
            for (int j = 0; j < 4; j++) {
                float2 ps = unpack2(s[j]);
                float2 pq = unpack2(q[j]);
                atomicAdd(&st[8 * cg + 2 * j], ps.x);
                atomicAdd(&st[8 * cg + 2 * j + 1], ps.y);
                atomicAdd(&st[64 + 8 * cg + 2 * j], pq.x);
                atomicAdd(&st[64 + 8 * cg + 2 * j + 1], pq.y);
            }
        }
    }

    // ---- staged coalesced store (no transpose array: acc IS row data) ----------
    __syncthreads();
    float* z_s = y_s;
#pragma unroll
    for (int i = 0; i < 4; i++) {
        float* row = z_s + (4 * ng + i) * ZPAD + 8 * cg;
#pragma unroll
        for (int j = 0; j < 4; j++)
            *(float2*)(row + 2 * j) = unpack2(acc[i][j]);
    }
    __syncthreads();
    {
        int r0 = tid >> 5;  // 8 rows per pass
#pragma unroll 4
        for (int p = 0; p < 16; p++) {
            int r = p * 8 + r0;
            int n = base + r;
            if (n < NN) {
                float2 v = *(const float2*)(z_s + r * ZPAD + 2 * lane);
                ((float2*)zout)[(size_t)n * 32 + lane] = v;
            }
        }
    }
}

__global__ void __launch_bounds__(256) kC(const float* __restrict__ gam,
                                          const float* __restrict__ bet,
                                          const float* __restrict__ fcW,
                                          int layer, int final_layer,
                                          float* __restrict__ out) {
    __shared__ float fw[640];
    __shared__ float sA[64], sB[64];
    int tid = threadIdx.x;
    const float* fsrc = fcW + (layer + 1) * 640;
    for (int i = tid; i < 640; i += 256) fw[i] = fsrc[i];
    if (tid < 64) {
        float s = g_stats[layer * 256 + 128 + tid];
        float q = g_stats[layer * 256 + 192 + tid];
        float mu = s * (1.f / NN);
        float var = q * (1.f / NN) - mu * mu;
        float a = rsqrtf(var + 1e-5f) * gam[tid];
        sA[tid] = a;
        sB[tid] = bet[tid] - mu * a;
    }
    __syncthreads();
    int n = blockIdx.x * 256 + tid;
    if (n >= NN) return;
    float o[10];
#pragma unroll
    for (int c = 0; c < 10; c++) o[c] = out[n * 10 + c];
    const float4* z4 = ((const float4*)g_z2) + (size_t)n * 16;
    float4* hout = ((float4*)g_h) + (size_t)n * 16;
#pragma unroll
    for (int kk = 0; kk < 16; kk++) {
        float4 v = z4[kk];
        int k0 = kk * 4;
        float h0 = fmaxf(fmaf(v.x, sA[k0 + 0], sB[k0 + 0]), 0.f);
        float h1 = fmaxf(fmaf(v.y, sA[k0 + 1], sB[k0 + 1]), 0.f);
        float h2 = fmaxf(fmaf(v.z, sA[k0 + 2], sB[k0 + 2]), 0.f);
        float h3 = fmaxf(fmaf(v.w, sA[k0 + 3], sB[k0 + 3]), 0.f);
        if (!final_layer) hout[kk] = make_float4(h0, h1, h2, h3);
        const float* r0 = fw + k0 * 10;
#pragma unroll
        for (int c = 0; c < 10; c++)
            o[c] += h0 * r0[c] + h1 * r0[10 + c] + h2 * r0[20 + c] + h3 * r0[30 + c];
    }
    if (final_layer) {
        float m = -1e30f;
#pragma unroll
        for (int c = 0; c < 10; c++) m = fmaxf(m, o[c]);
        float s = 0.f;
#pragma unroll
        for (int c = 0; c < 10; c++) s += expf(o[c] - m);
        float lse = m + logf(s);
#pragma unroll
        for (int c = 0; c < 10; c++) o[c] -= lse;
    }
#pragma unroll
    for (int c = 0; c < 10; c++) out[n * 10 + c] = o[c];
}

extern "C" void kernel_launch(void* const* d_in, const int* in_sizes, int n_in,
                              void* d_out, int out_size) {
    const float* x   = (const float*)d_in[0];
    const int*   ei  = (const int*)d_in[1];
    const float* W1  = (const float*)d_in[2];
    const float* b1  = (const float*)d_in[3];
    const float* g1  = (const float*)d_in[4];
    const float* be1 = (const float*)d_in[5];
    const float* W2  = (const float*)d_in[6];
    const float* b2  = (const float*)d_in[7];
    const float* gbn = (const float*)d_in[8];
    const float* bbn = (const float*)d_in[9];
    const float* fcW = (const float*)d_in[10];
    const float* fcb = (const float*)d_in[11];
    float* out = (float*)d_out;

    const int GB  = (NN * 32 + 255) / 256;
    const int GGB = (NN + GNPB - 1) / GNPB;
    const int CB  = (NN + 255) / 256;

    kzero<<<(NN + 1023) / 1024, 1024>>>();
    kfill<<<(EE + 255) / 256, 256>>>(ei);
    kinit<<<CB, 256>>>(x, fcW, fcb, out);
    for (int l = 0; l < LL; l++) {
        int use_x = (l == 0) ? 1 : 0;
        kgather<<<GB, 256>>>(x, use_x);
        kG<<<GGB, 256>>>(W1 + l * 4096, b1 + l * 64, nullptr, nullptr, l, 0);
        kG<<<GGB, 256>>>(W2 + l * 4096, b2 + l * 64, g1 + l * 64, be1 + l * 64, l, 1);
        kC<<<CB, 256>>>(gbn + l * 64, bbn + l * 64, fcW, l, (l == LL - 1) ? 1 : 0, out);
    }
}